// round 13
// baseline (speedup 1.0000x reference)
#include <cuda_runtime.h>
#include <cstdint>

#define NP      32768
#define NB      128
#define NC      6
#define TOPK    400
#define KEEPK   200
#define NTH     1024
#define EQCAP   2048
#define EQ2CAP  512
#define APT     8
#define SUPROWS 416
#define CONF_TH 0.5f
#define NMS_TH  0.5f
#define BIGF    1.0e9f
#define NEGF    (-1.0e9f)

// global scratch (static arrays, zero-initialized at module load; no runtime alloc)
__device__ unsigned int g_keys[(size_t)NB * NP];     // 16 MB
__device__ unsigned int g_hist[(size_t)NB * 4096];   // 2 MB

__device__ __forceinline__ unsigned int fkey(float x) {
    unsigned int u = __float_as_uint(x);
    return (u & 0x80000000u) ? ~u : (u | 0x80000000u);
}
__device__ __forceinline__ float ikey(unsigned int k) {
    unsigned int u = (k & 0x80000000u) ? (k & 0x7fffffffu) : ~k;
    return __uint_as_float(u);
}
__device__ __forceinline__ unsigned long long packci(unsigned int k, unsigned int idx) {
    return ((unsigned long long)k << 32) | (unsigned int)(~idx);
}
// bits j (= w*32+l) with j > i within word w of row i
__device__ __forceinline__ unsigned int rowmask(int i, int w) {
    int wi = i >> 5;
    if (w > wi) return 0xFFFFFFFFu;
    if (w < wi) return 0u;
    return ~(unsigned int)(((unsigned long long)2 << (i & 31)) - 1ull);
}

// ---------------- kernel A: streaming keys + per-image histogram ----------------
__global__ __launch_bounds__(NTH, 2)
void key_hist_kernel(const float* __restrict__ pred) {
    __shared__ unsigned int h[4096];
    int t = threadIdx.x;
    for (int i = t; i < 4096; i += NTH) h[i] = 0;
    __syncthreads();
    int img = blockIdx.x >> 2;
    int base = blockIdx.x * (NTH * APT) + t;
#pragma unroll
    for (int j = 0; j < APT; ++j) {
        int i = base + j * NTH;
        float2 cf = *reinterpret_cast<const float2*>(pred + (size_t)i * 6 + 4);
        float sc = fmaxf(cf.x, cf.y);
        float m = (sc > CONF_TH) ? sc : NEGF;
        unsigned int k = fkey(m);
        g_keys[i] = k;
        unsigned int bin = k >> 20;
        unsigned int mm = __match_any_sync(0xffffffffu, bin);
        int leader = __ffs(mm) - 1;
        if ((t & 31) == leader) atomicAdd(&h[bin], (unsigned int)__popc(mm));
    }
    __syncthreads();
    for (int i = t; i < 4096; i += NTH) {
        unsigned int v = h[i];
        if (v) atomicAdd(&g_hist[(size_t)img * 4096 + i], v);
    }
}

// ---------------- kernel B: per-image selection + NMS ----------------
struct __align__(16) SmemT {
    union __align__(16) {
        struct {
            unsigned int hist[4096];   // 16 KB
            unsigned int sscan[64];
        } sel;
        struct { unsigned long long eq[EQCAP]; unsigned long long eq2[EQ2CAP]; } eqs;  // 20 KB
        unsigned int sup[SUPROWS * 16];  // 26.6 KB (13 words used per row)
    } u;
    unsigned long long sortbuf[512];
    float4 cbox[SUPROWS];     // rows 400..415 zeroed
    float  carea[SUPROWS];
    float  cscore[TOPK];
    float  clabel[TOPK];
    unsigned int hist2[256];  // second-level eq histogram (outside union!)
    unsigned int keepw[16];
    unsigned int woff[14];
    unsigned int s_mkept;
    int s_bin;
    int s_gt;
    int s_d2;
    unsigned int s_g2;
    unsigned int s_cnt;
    unsigned int s_eq;
    unsigned int s_cnt2;
    unsigned int s_eq2;
};

__device__ void find_bin(SmemT& s, int K, int& bin_out, int& gt_out) {
    int t = threadIdx.x;
    int lane = t & 31;
    int w = t >> 5;
    unsigned int c[4];
    unsigned int sum = 0;
#pragma unroll
    for (int j = 0; j < 4; j++) { c[j] = s.u.sel.hist[4 * t + j]; sum += c[j]; }
    unsigned int suf = sum;
#pragma unroll
    for (int off = 1; off < 32; off <<= 1) {
        unsigned int v = __shfl_down_sync(0xffffffffu, suf, off);
        if (lane + off < 32) suf += v;
    }
    if (lane == 0) s.u.sel.sscan[w] = suf;
    if (t == 0) s.s_bin = -1;
    __syncthreads();
    if (w == 0) {
        unsigned int wt = s.u.sel.sscan[lane];
        unsigned int ws = wt;
#pragma unroll
        for (int off = 1; off < 32; off <<= 1) {
            unsigned int v = __shfl_down_sync(0xffffffffu, ws, off);
            if (lane + off < 32) ws += v;
        }
        s.u.sel.sscan[32 + lane] = ws - wt;
    }
    __syncthreads();
    unsigned int after = (suf - sum) + s.u.sel.sscan[32 + w];
    unsigned int run = after;
    int best = -1;
    unsigned int bestgt = 0;
#pragma unroll
    for (int j = 3; j >= 0; j--) {
        unsigned int cnt = c[j];
        if (best < 0 && run + cnt >= (unsigned int)K) { best = 4 * t + j; bestgt = run; }
        run += cnt;
    }
    if (best >= 0) atomicMax(&s.s_bin, best);
    __syncthreads();
    if (best >= 0 && best == s.s_bin) s.s_gt = (int)bestgt;
    __syncthreads();
    bin_out = s.s_bin;
    gt_out = s.s_gt;
}

__global__ __launch_bounds__(NTH, 1)
void box_selector_kernel(const float* __restrict__ pred,
                         const float* __restrict__ priors,
                         float* __restrict__ out) {
    __shared__ SmemT s;
    const int t = threadIdx.x;
    const int b = blockIdx.x;
    const float* pb = pred + (size_t)b * NP * NC;
    const unsigned int* keys = g_keys + (size_t)b * NP;

    // ---------- init + hist load (re-zero global hist for next launch) ----------
    if (t < 16) {
        s.keepw[t] = (t == 12) ? 0xFFFF0000u : 0u;
        s.cbox[TOPK + t] = make_float4(0.f, 0.f, 0.f, 0.f);
        s.carea[TOPK + t] = 0.f;
    }
    if (t < 256) s.hist2[t] = 0u;
    for (int i = t; i < 4096; i += NTH) {
        s.u.sel.hist[i] = g_hist[(size_t)b * 4096 + i];
        g_hist[(size_t)b * 4096 + i] = 0u;
    }
    __syncthreads();
    int d1, g1;
    find_bin(s, TOPK, d1, g1);
    int k1 = TOPK - g1;

    // ---------- merged scan: >d1 -> sortbuf (packed), ==d1 -> eq (packed) ----------
    if (t == 0) { s.s_cnt = 0; s.s_eq = 0; }
    __syncthreads();
    {
        const uint4* keys4 = reinterpret_cast<const uint4*>(keys);
#pragma unroll
        for (int j = 0; j < (NP / 4) / NTH; ++j) {
            int n4 = t + j * NTH;
            uint4 kv = keys4[n4];
            int base = n4 * 4;
            unsigned int kk[4] = {kv.x, kv.y, kv.z, kv.w};
#pragma unroll
            for (int l = 0; l < 4; ++l) {
                unsigned int k = kk[l];
                int top = (int)(k >> 20);
                if (top > d1) {
                    unsigned int p = atomicAdd(&s.s_cnt, 1u);
                    s.sortbuf[p] = packci(k, (unsigned int)(base + l));
                } else if (top == d1) {
                    unsigned int e = atomicAdd(&s.s_eq, 1u);
                    if (e < EQCAP) s.u.eqs.eq[e] = packci(k, (unsigned int)(base + l));
                }
            }
        }
    }
    __syncthreads();
    int eqcnt = (int)s.s_eq;

    if (eqcnt <= EQCAP) {
        // ---- two-level refine: 256-bin histogram of key bits [12:19] ----
        for (int me = t; me < eqcnt; me += NTH)
            atomicAdd(&s.hist2[(unsigned int)((s.u.eqs.eq[me] >> 44) & 0xFFu)], 1u);
        __syncthreads();
        if (t < 32) {
            unsigned int c[8];
            unsigned int sum = 0;
#pragma unroll
            for (int q = 0; q < 8; ++q) { c[q] = s.hist2[8 * t + q]; sum += c[q]; }
            unsigned int suf = sum;
#pragma unroll
            for (int off = 1; off < 32; off <<= 1) {
                unsigned int v = __shfl_down_sync(0xffffffffu, suf, off);
                if (t + off < 32) suf += v;
            }
            unsigned int after = suf - sum;
            unsigned int run = after;
            int best = -1;
            unsigned int bg = 0;
#pragma unroll
            for (int q = 7; q >= 0; --q) {
                unsigned int cnt = c[q];
                if (best < 0 && run + cnt >= (unsigned int)k1) { best = 8 * t + q; bg = run; }
                run += cnt;
            }
            int bmax = best;
#pragma unroll
            for (int off = 16; off; off >>= 1) bmax = max(bmax, __shfl_xor_sync(0xffffffffu, bmax, off));
            if (best >= 0 && best == bmax) { s.s_d2 = best; s.s_g2 = bg; }
        }
        if (t == 0) { s.s_cnt2 = 0; s.s_eq2 = 0; }
        __syncthreads();
        int d2 = s.s_d2;
        int k2 = k1 - (int)s.s_g2;
        int c2 = (int)s.hist2[d2];

        if (c2 <= EQ2CAP) {
            for (int me = t; me < eqcnt; me += NTH) {
                unsigned long long v = s.u.eqs.eq[me];
                int mid = (int)((v >> 44) & 0xFFu);
                if (mid > d2) {
                    unsigned int p = atomicAdd(&s.s_cnt2, 1u);
                    s.sortbuf[g1 + p] = v;
                } else if (mid == d2) {
                    unsigned int e = atomicAdd(&s.s_eq2, 1u);
                    s.u.eqs.eq2[e] = v;
                }
            }
            __syncthreads();
            // exact rank of ties (c2 typically tiny)
            for (int me = t; me < c2; me += NTH) {
                unsigned long long v = s.u.eqs.eq2[me];
                int rank = 0;
                for (int j = 0; j < c2; ++j) rank += (s.u.eqs.eq2[j] > v) ? 1 : 0;
                if (rank < k2) {
                    unsigned int p = atomicAdd(&s.s_cnt2, 1u);
                    s.sortbuf[g1 + p] = v;
                }
            }
        } else {
            // pathological tie storm: direct rank among mid==d2 over the full eq
            for (int me = t; me < eqcnt; me += NTH) {
                unsigned long long v = s.u.eqs.eq[me];
                int mid = (int)((v >> 44) & 0xFFu);
                if (mid > d2) {
                    unsigned int p = atomicAdd(&s.s_cnt2, 1u);
                    s.sortbuf[g1 + p] = v;
                } else if (mid == d2) {
                    int rank = 0;
                    for (int j = 0; j < eqcnt; ++j) {
                        unsigned long long w2 = s.u.eqs.eq[j];
                        if (((int)((w2 >> 44) & 0xFFu) == d2) && w2 > v) rank++;
                    }
                    if (rank < k2) {
                        unsigned int p = atomicAdd(&s.s_cnt2, 1u);
                        s.sortbuf[g1 + p] = v;
                    }
                }
            }
        }
    } else {
        // ---------- fallback: radix refine within bin d1 from global keys (rare) ----------
        __syncthreads();
        for (int i = t; i < 4096; i += NTH) s.u.sel.hist[i] = 0;
        __syncthreads();
        for (int n = t; n < NP; n += NTH) {
            unsigned int k = keys[n];
            if ((int)(k >> 20) == d1) atomicAdd(&s.u.sel.hist[(k >> 8) & 0xfffu], 1u);
        }
        __syncthreads();
        int d2, g2;
        find_bin(s, k1, d2, g2);
        int k2 = k1 - g2;
        unsigned int P24 = ((unsigned int)d1 << 12) | (unsigned int)d2;
        __syncthreads();
        for (int i = t; i < 4096; i += NTH) s.u.sel.hist[i] = 0;
        __syncthreads();
        for (int n = t; n < NP; n += NTH) {
            unsigned int k = keys[n];
            if ((k >> 8) == P24) atomicAdd(&s.u.sel.hist[k & 0xffu], 1u);
        }
        __syncthreads();
        int d3, g3;
        find_bin(s, k2, d3, g3);
        int need = k2 - g3;
        unsigned int KP = (P24 << 8) | (unsigned int)d3;
        if (t == 0) s.s_cnt = 0;
        __syncthreads();
        for (int n = t; n < NP; n += NTH) {
            unsigned int k = keys[n];
            if ((int)(k >> 20) == d1 && k > KP) {
                unsigned int p = atomicAdd(&s.s_cnt, 1u);
                s.sortbuf[g1 + p] = packci(k, (unsigned int)n);
            }
        }
        __syncthreads();
        if (t < 32) {
            int taken = 0;
            int slot0 = g1 + (k1 - need);
            for (int base2 = 0; base2 < NP && taken < need; base2 += 32) {
                unsigned int k = keys[base2 + t];
                bool e = (k == KP);
                unsigned int bal = __ballot_sync(0xffffffffu, e);
                int rank = __popc(bal & ((1u << t) - 1u));
                if (e && taken + rank < need)
                    s.sortbuf[slot0 + taken + rank] = packci(KP, (unsigned int)(base2 + t));
                taken += __popc(bal);
            }
        }
    }
    __syncthreads();

    // ---------- fused sort1-rank + decode: exactly 400 entries = 25 full warps ----------
    if (t < 2 * TOPK) {
        int e = t >> 1;
        int p = t & 1;
        unsigned long long my = s.sortbuf[e];
        const ulonglong2* sb2 = reinterpret_cast<const ulonglong2*>(s.sortbuf) + p * 100;
        int rank = 0;
#pragma unroll 4
        for (int j = 0; j < 100; ++j) {
            ulonglong2 v = sb2[j];
            rank += (v.x > my) ? 1 : 0;
            rank += (v.y > my) ? 1 : 0;
        }
        rank += __shfl_xor_sync(0xffffffffu, rank, 1);
        if (p == 0) {
            unsigned int k = (unsigned int)(my >> 32);
            unsigned int idx = ~(unsigned int)my;
            float sc = ikey(k);
            float4 pr = reinterpret_cast<const float4*>(priors)[idx];
            const float2* pp2 = reinterpret_cast<const float2*>(pb + (size_t)idx * 6);
            float2 ab = pp2[0];
            float2 cd = pp2[1];
            float2 ef = pp2[2];
            float cx = pr.x + ab.x * 0.1f * pr.z;
            float cy = pr.y + ab.y * 0.1f * pr.w;
            float w  = pr.z * expf(cd.x * 0.2f);
            float h  = pr.w * expf(cd.y * 0.2f);
            float4 bx = make_float4(cx - 0.5f * w, cy - 0.5f * h, cx + 0.5f * w, cy + 0.5f * h);
            s.cbox[rank]  = bx;
            s.carea[rank] = (bx.z - bx.x) * (bx.w - bx.y);
            s.cscore[rank] = sc;
            s.clabel[rank] = (ef.y > ef.x) ? 1.0f : 0.0f;
            if (!(sc > CONF_TH)) atomicOr(&s.keepw[rank >> 5], 1u << (rank & 31));
        }
    }
    __syncthreads();

    // ---------- suppression bit matrix: 2 rows per warp-pass ----------
    {
        int wi = t >> 5;
        int lane = t & 31;
        for (int ip = wi; ip < TOPK / 2; ip += 32) {
            int iA = 2 * ip, iB = iA + 1;
            float4 bA = s.cbox[iA]; float aA = s.carea[iA];
            float4 bB = s.cbox[iB]; float aB = s.carea[iB];
            int w0 = iA >> 5;
            for (int word = w0; word < 13; ++word) {
                int j = (word << 5) | lane;
                float4 bj = s.cbox[j];
                float aj = s.carea[j];
                // row A
                float iwA = fmaxf(fminf(bA.z, bj.z) - fmaxf(bA.x, bj.x), 0.0f);
                float ihA = fmaxf(fminf(bA.w, bj.w) - fmaxf(bA.y, bj.y), 0.0f);
                float inA = iwA * ihA;
                float ssA = aA + aj;
                float mA  = __fmaf_rn(3.0f, inA, -ssA);
                float tA  = 1e-4f * ssA + 1e-20f;
                bool supA;
                if (mA > tA)        supA = true;
                else if (mA >= -tA) supA = (inA / (ssA - inA + 1e-12f)) > NMS_TH;
                else                supA = false;
                // row B
                float iwB = fmaxf(fminf(bB.z, bj.z) - fmaxf(bB.x, bj.x), 0.0f);
                float ihB = fmaxf(fminf(bB.w, bj.w) - fmaxf(bB.y, bj.y), 0.0f);
                float inB = iwB * ihB;
                float ssB = aB + aj;
                float mB  = __fmaf_rn(3.0f, inB, -ssB);
                float tB  = 1e-4f * ssB + 1e-20f;
                bool supB;
                if (mB > tB)        supB = true;
                else if (mB >= -tB) supB = (inB / (ssB - inB + 1e-12f)) > NMS_TH;
                else                supB = false;
                unsigned int balA = __ballot_sync(0xffffffffu, supA);
                unsigned int balB = __ballot_sync(0xffffffffu, supB);
                if (lane == 0) {
                    s.u.sup[iA * 16 + word] = balA & rowmask(iA, word);
                    s.u.sup[iB * 16 + word] = balB & rowmask(iB, word);
                }
            }
        }
    }
    __syncthreads();

    // ---------- single-warp greedy NMS reduce (no block barriers inside) ----------
    if (t < 32) {
        int lane = t;
        unsigned int rm = (lane < 13) ? s.keepw[lane] : 0u;
#pragma unroll 1
        for (int g = 0; g < 13; ++g) {
            unsigned int m = __shfl_sync(0xffffffffu, rm, g);
            const unsigned int* rowg = &s.u.sup[(g * 32) * 16 + g];
#pragma unroll
            for (int ch = 0; ch < 4; ++ch) {
                unsigned int rr[8];
#pragma unroll
                for (int q = 0; q < 8; ++q) rr[q] = rowg[(ch * 8 + q) * 16];
#pragma unroll
                for (int q = 0; q < 8; ++q) {
                    int bb = ch * 8 + q;
                    if (!((m >> bb) & 1u)) m |= rr[q];
                }
            }
            if (lane > g && lane < 13) {
                unsigned int acc = 0;
                const unsigned int* col = &s.u.sup[(g * 32) * 16 + lane];
#pragma unroll
                for (int r = 0; r < 32; ++r) {
                    unsigned int v = col[r * 16];
                    acc |= ((m >> r) & 1u) ? 0u : v;
                }
                rm |= acc;
            }
            if (lane == g) rm = m;
        }
        if (lane < 13) s.keepw[lane] = rm;
    }
    __syncthreads();

    // ---------- output: kept-only compaction + warp-uniform pair-split ranking ----------
    if (t == 0) {
        unsigned int acc = 0;
#pragma unroll
        for (int w = 0; w < 13; ++w) { s.woff[w] = acc; acc += (unsigned)__popc(~s.keepw[w]); }
        s.s_mkept = acc;
    }
    __syncthreads();
    int mk = (int)s.s_mkept;
    if (t < TOPK) {
        bool kp = !((s.keepw[t >> 5] >> (t & 31)) & 1u);
        if (kp) {
            unsigned int before = (unsigned)__popc(~s.keepw[t >> 5] & ((1u << (t & 31)) - 1u));
            int pos = (int)(s.woff[t >> 5] + before);
            s.sortbuf[pos] = ((unsigned long long)__float_as_uint(s.cscore[t]) << 32) | (unsigned int)t;
        }
    }
    if (t < 512 && t >= mk) s.sortbuf[t] = 0xFFFFFFFFFFFFFFFFull;
    __syncthreads();
    {
        int tot2 = 2 * mk;                 // even -> lane pairs both active/inactive
        int tlim2 = (tot2 + 31) & ~31;     // warp-aligned participation
        if (t < tlim2) {
            int e = t >> 1;                 // e <= 415 < 512 (padded region valid)
            int p = t & 1;
            bool act = t < tot2;
            unsigned long long my = s.sortbuf[e];
            const ulonglong2* sb2 = reinterpret_cast<const ulonglong2*>(s.sortbuf);
            int vreal = (mk + 1) >> 1;
            int jmax = vreal - p * 128;
            jmax = jmax < 0 ? 0 : (jmax > 128 ? 128 : jmax);
            int rank = 0;
            for (int j = 0; j < jmax; ++j) {
                ulonglong2 v = sb2[p * 128 + j];
                rank += (v.x < my) ? 1 : 0;
                rank += (v.y < my) ? 1 : 0;
            }
            rank += __shfl_xor_sync(0xffffffffu, rank, 1);
            if (act && p == 0 && rank < KEEPK) {
                int c = (int)(unsigned int)(my & 0xffffffffu);
                float4 bx = s.cbox[c];
                float* o = out + ((size_t)b * KEEPK + rank) * 6;
                o[0] = s.clabel[c];
                o[1] = s.cscore[c];
                o[2] = bx.x; o[3] = bx.y; o[4] = bx.z; o[5] = bx.w;
            }
        }
    }
    if (t < KEEPK && t >= mk) {
        float* o = out + ((size_t)b * KEEPK + t) * 6;
        o[0] = 0.0f; o[1] = 0.0f; o[2] = 0.0f;
        o[3] = 0.0f; o[4] = 0.0f; o[5] = 0.0f;
    }
}

extern "C" void kernel_launch(void* const* d_in, const int* in_sizes, int n_in,
                              void* d_out, int out_size) {
    const float* pred = (const float*)d_in[0];
    const float* pri  = (const float*)d_in[1];
    if (n_in >= 2 && in_sizes[0] < in_sizes[1]) {
        const float* tmp = pred; pred = pri; pri = tmp;
    }
    float* out = (float*)d_out;
    int gridA = (NB * NP) / (NTH * APT);   // 512 blocks, 4 per image
    key_hist_kernel<<<gridA, NTH>>>(pred);
    box_selector_kernel<<<NB, NTH>>>(pred, pri, out);
}

// round 14
// speedup vs baseline: 1.3026x; 1.3026x over previous
#include <cuda_runtime.h>
#include <cstdint>

#define NP      32768
#define NB      128
#define NC      6
#define TOPK    400
#define KEEPK   200
#define NTH     1024
#define EQCAP   2048
#define EQ2CAP  512
#define APT     8
#define SUPROWS 416
#define CONF_TH 0.5f
#define NMS_TH  0.5f
#define BIGF    1.0e9f
#define NEGF    (-1.0e9f)

// global scratch (static arrays, zero-initialized at module load; no runtime alloc)
__device__ unsigned int g_keys[(size_t)NB * NP];     // 16 MB
__device__ unsigned int g_hist[(size_t)NB * 4096];   // 2 MB

__device__ __forceinline__ unsigned int fkey(float x) {
    unsigned int u = __float_as_uint(x);
    return (u & 0x80000000u) ? ~u : (u | 0x80000000u);
}
__device__ __forceinline__ float ikey(unsigned int k) {
    unsigned int u = (k & 0x80000000u) ? (k & 0x7fffffffu) : ~k;
    return __uint_as_float(u);
}
__device__ __forceinline__ unsigned long long packci(unsigned int k, unsigned int idx) {
    return ((unsigned long long)k << 32) | (unsigned int)(~idx);
}
// bits j (= w*32+l) with j > i within word w of row i
__device__ __forceinline__ unsigned int rowmask(int i, int w) {
    int wi = i >> 5;
    if (w > wi) return 0xFFFFFFFFu;
    if (w < wi) return 0u;
    return ~(unsigned int)(((unsigned long long)2 << (i & 31)) - 1ull);
}

// ---------------- kernel A: streaming keys + per-image histogram ----------------
// __ldcs on pred is LOAD-BEARING: evict-first keeps the 96MB stream out of L2,
// preserving L2 residency for g_keys across graph replays (R12 vs R13: ~20us).
__global__ __launch_bounds__(NTH, 2)
void key_hist_kernel(const float* __restrict__ pred) {
    __shared__ unsigned int h[4096];
    int t = threadIdx.x;
    for (int i = t; i < 4096; i += NTH) h[i] = 0;
    __syncthreads();
    int img = blockIdx.x >> 2;
    int base = blockIdx.x * (NTH * APT) + t;
#pragma unroll
    for (int j = 0; j < APT; ++j) {
        int i = base + j * NTH;
        float2 cf = __ldcs(reinterpret_cast<const float2*>(pred + (size_t)i * 6 + 4));
        float sc = fmaxf(cf.x, cf.y);
        float m = (sc > CONF_TH) ? sc : NEGF;
        unsigned int k = fkey(m);
        g_keys[i] = k;
        unsigned int bin = k >> 20;
        unsigned int mm = __match_any_sync(0xffffffffu, bin);
        int leader = __ffs(mm) - 1;
        if ((t & 31) == leader) atomicAdd(&h[bin], (unsigned int)__popc(mm));
    }
    __syncthreads();
    for (int i = t; i < 4096; i += NTH) {
        unsigned int v = h[i];
        if (v) atomicAdd(&g_hist[(size_t)img * 4096 + i], v);
    }
}

// ---------------- kernel B: per-image selection + NMS ----------------
struct __align__(16) SmemT {
    union __align__(16) {
        struct {
            unsigned int hist[4096];   // 16 KB
            unsigned int sscan[64];
        } sel;
        struct { unsigned long long eq[EQCAP]; unsigned long long eq2[EQ2CAP]; } eqs;  // 20 KB
        unsigned int sup[SUPROWS * 16];  // 26.6 KB (13 words used per row)
    } u;
    unsigned long long sortbuf[512];
    float4 cbox[SUPROWS];     // rows 400..415 zeroed
    float  carea[SUPROWS];
    float  cscore[TOPK];
    float  clabel[TOPK];
    unsigned int hist2[256];  // second-level eq histogram (outside union!)
    unsigned int keepw[16];
    unsigned int woff[14];
    unsigned int s_mkept;
    int s_bin;
    int s_gt;
    int s_d2;
    unsigned int s_g2;
    unsigned int s_cnt;
    unsigned int s_eq;
    unsigned int s_cnt2;
    unsigned int s_eq2;
};

__device__ void find_bin(SmemT& s, int K, int& bin_out, int& gt_out) {
    int t = threadIdx.x;
    int lane = t & 31;
    int w = t >> 5;
    unsigned int c[4];
    unsigned int sum = 0;
#pragma unroll
    for (int j = 0; j < 4; j++) { c[j] = s.u.sel.hist[4 * t + j]; sum += c[j]; }
    unsigned int suf = sum;
#pragma unroll
    for (int off = 1; off < 32; off <<= 1) {
        unsigned int v = __shfl_down_sync(0xffffffffu, suf, off);
        if (lane + off < 32) suf += v;
    }
    if (lane == 0) s.u.sel.sscan[w] = suf;
    if (t == 0) s.s_bin = -1;
    __syncthreads();
    if (w == 0) {
        unsigned int wt = s.u.sel.sscan[lane];
        unsigned int ws = wt;
#pragma unroll
        for (int off = 1; off < 32; off <<= 1) {
            unsigned int v = __shfl_down_sync(0xffffffffu, ws, off);
            if (lane + off < 32) ws += v;
        }
        s.u.sel.sscan[32 + lane] = ws - wt;
    }
    __syncthreads();
    unsigned int after = (suf - sum) + s.u.sel.sscan[32 + w];
    unsigned int run = after;
    int best = -1;
    unsigned int bestgt = 0;
#pragma unroll
    for (int j = 3; j >= 0; j--) {
        unsigned int cnt = c[j];
        if (best < 0 && run + cnt >= (unsigned int)K) { best = 4 * t + j; bestgt = run; }
        run += cnt;
    }
    if (best >= 0) atomicMax(&s.s_bin, best);
    __syncthreads();
    if (best >= 0 && best == s.s_bin) s.s_gt = (int)bestgt;
    __syncthreads();
    bin_out = s.s_bin;
    gt_out = s.s_gt;
}

__global__ __launch_bounds__(NTH, 1)
void box_selector_kernel(const float* __restrict__ pred,
                         const float* __restrict__ priors,
                         float* __restrict__ out) {
    __shared__ SmemT s;
    const int t = threadIdx.x;
    const int b = blockIdx.x;
    const float* pb = pred + (size_t)b * NP * NC;
    const unsigned int* keys = g_keys + (size_t)b * NP;

    // ---------- init + hist load (re-zero global hist for next launch) ----------
    if (t < 16) {
        s.keepw[t] = (t == 12) ? 0xFFFF0000u : 0u;
        s.cbox[TOPK + t] = make_float4(0.f, 0.f, 0.f, 0.f);
        s.carea[TOPK + t] = 0.f;
    }
    if (t < 256) s.hist2[t] = 0u;
    for (int i = t; i < 4096; i += NTH) {
        s.u.sel.hist[i] = g_hist[(size_t)b * 4096 + i];
        g_hist[(size_t)b * 4096 + i] = 0u;
    }
    __syncthreads();
    int d1, g1;
    find_bin(s, TOPK, d1, g1);
    int k1 = TOPK - g1;

    // ---------- merged scan: >d1 -> sortbuf (packed), ==d1 -> eq (packed) ----------
    if (t == 0) { s.s_cnt = 0; s.s_eq = 0; }
    __syncthreads();
    {
        const uint4* keys4 = reinterpret_cast<const uint4*>(keys);
#pragma unroll
        for (int j = 0; j < (NP / 4) / NTH; ++j) {
            int n4 = t + j * NTH;
            uint4 kv = keys4[n4];
            int base = n4 * 4;
            unsigned int kk[4] = {kv.x, kv.y, kv.z, kv.w};
#pragma unroll
            for (int l = 0; l < 4; ++l) {
                unsigned int k = kk[l];
                int top = (int)(k >> 20);
                if (top > d1) {
                    unsigned int p = atomicAdd(&s.s_cnt, 1u);
                    s.sortbuf[p] = packci(k, (unsigned int)(base + l));
                } else if (top == d1) {
                    unsigned int e = atomicAdd(&s.s_eq, 1u);
                    if (e < EQCAP) s.u.eqs.eq[e] = packci(k, (unsigned int)(base + l));
                }
            }
        }
    }
    __syncthreads();
    int eqcnt = (int)s.s_eq;

    if (eqcnt <= EQCAP) {
        // ---- two-level refine: 256-bin histogram of key bits [12:19] ----
        for (int me = t; me < eqcnt; me += NTH)
            atomicAdd(&s.hist2[(unsigned int)((s.u.eqs.eq[me] >> 44) & 0xFFu)], 1u);
        __syncthreads();
        if (t < 32) {
            unsigned int c[8];
            unsigned int sum = 0;
#pragma unroll
            for (int q = 0; q < 8; ++q) { c[q] = s.hist2[8 * t + q]; sum += c[q]; }
            unsigned int suf = sum;
#pragma unroll
            for (int off = 1; off < 32; off <<= 1) {
                unsigned int v = __shfl_down_sync(0xffffffffu, suf, off);
                if (t + off < 32) suf += v;
            }
            unsigned int after = suf - sum;
            unsigned int run = after;
            int best = -1;
            unsigned int bg = 0;
#pragma unroll
            for (int q = 7; q >= 0; --q) {
                unsigned int cnt = c[q];
                if (best < 0 && run + cnt >= (unsigned int)k1) { best = 8 * t + q; bg = run; }
                run += cnt;
            }
            int bmax = best;
#pragma unroll
            for (int off = 16; off; off >>= 1) bmax = max(bmax, __shfl_xor_sync(0xffffffffu, bmax, off));
            if (best >= 0 && best == bmax) { s.s_d2 = best; s.s_g2 = bg; }
        }
        if (t == 0) { s.s_cnt2 = 0; s.s_eq2 = 0; }
        __syncthreads();
        int d2 = s.s_d2;
        int k2 = k1 - (int)s.s_g2;
        int c2 = (int)s.hist2[d2];

        if (c2 <= EQ2CAP) {
            for (int me = t; me < eqcnt; me += NTH) {
                unsigned long long v = s.u.eqs.eq[me];
                int mid = (int)((v >> 44) & 0xFFu);
                if (mid > d2) {
                    unsigned int p = atomicAdd(&s.s_cnt2, 1u);
                    s.sortbuf[g1 + p] = v;
                } else if (mid == d2) {
                    unsigned int e = atomicAdd(&s.s_eq2, 1u);
                    s.u.eqs.eq2[e] = v;
                }
            }
            __syncthreads();
            // exact rank of ties (c2 typically tiny)
            for (int me = t; me < c2; me += NTH) {
                unsigned long long v = s.u.eqs.eq2[me];
                int rank = 0;
                for (int j = 0; j < c2; ++j) rank += (s.u.eqs.eq2[j] > v) ? 1 : 0;
                if (rank < k2) {
                    unsigned int p = atomicAdd(&s.s_cnt2, 1u);
                    s.sortbuf[g1 + p] = v;
                }
            }
        } else {
            // pathological tie storm: direct rank among mid==d2 over the full eq
            for (int me = t; me < eqcnt; me += NTH) {
                unsigned long long v = s.u.eqs.eq[me];
                int mid = (int)((v >> 44) & 0xFFu);
                if (mid > d2) {
                    unsigned int p = atomicAdd(&s.s_cnt2, 1u);
                    s.sortbuf[g1 + p] = v;
                } else if (mid == d2) {
                    int rank = 0;
                    for (int j = 0; j < eqcnt; ++j) {
                        unsigned long long w2 = s.u.eqs.eq[j];
                        if (((int)((w2 >> 44) & 0xFFu) == d2) && w2 > v) rank++;
                    }
                    if (rank < k2) {
                        unsigned int p = atomicAdd(&s.s_cnt2, 1u);
                        s.sortbuf[g1 + p] = v;
                    }
                }
            }
        }
    } else {
        // ---------- fallback: radix refine within bin d1 from global keys (rare) ----------
        __syncthreads();
        for (int i = t; i < 4096; i += NTH) s.u.sel.hist[i] = 0;
        __syncthreads();
        for (int n = t; n < NP; n += NTH) {
            unsigned int k = keys[n];
            if ((int)(k >> 20) == d1) atomicAdd(&s.u.sel.hist[(k >> 8) & 0xfffu], 1u);
        }
        __syncthreads();
        int d2, g2;
        find_bin(s, k1, d2, g2);
        int k2 = k1 - g2;
        unsigned int P24 = ((unsigned int)d1 << 12) | (unsigned int)d2;
        __syncthreads();
        for (int i = t; i < 4096; i += NTH) s.u.sel.hist[i] = 0;
        __syncthreads();
        for (int n = t; n < NP; n += NTH) {
            unsigned int k = keys[n];
            if ((k >> 8) == P24) atomicAdd(&s.u.sel.hist[k & 0xffu], 1u);
        }
        __syncthreads();
        int d3, g3;
        find_bin(s, k2, d3, g3);
        int need = k2 - g3;
        unsigned int KP = (P24 << 8) | (unsigned int)d3;
        if (t == 0) s.s_cnt = 0;
        __syncthreads();
        for (int n = t; n < NP; n += NTH) {
            unsigned int k = keys[n];
            if ((int)(k >> 20) == d1 && k > KP) {
                unsigned int p = atomicAdd(&s.s_cnt, 1u);
                s.sortbuf[g1 + p] = packci(k, (unsigned int)n);
            }
        }
        __syncthreads();
        if (t < 32) {
            int taken = 0;
            int slot0 = g1 + (k1 - need);
            for (int base2 = 0; base2 < NP && taken < need; base2 += 32) {
                unsigned int k = keys[base2 + t];
                bool e = (k == KP);
                unsigned int bal = __ballot_sync(0xffffffffu, e);
                int rank = __popc(bal & ((1u << t) - 1u));
                if (e && taken + rank < need)
                    s.sortbuf[slot0 + taken + rank] = packci(KP, (unsigned int)(base2 + t));
                taken += __popc(bal);
            }
        }
    }
    __syncthreads();

    // ---------- fused sort1-rank + decode: exactly 400 entries = 25 full warps ----------
    if (t < 2 * TOPK) {
        int e = t >> 1;
        int p = t & 1;
        unsigned long long my = s.sortbuf[e];
        const ulonglong2* sb2 = reinterpret_cast<const ulonglong2*>(s.sortbuf) + p * 100;
        int rank = 0;
#pragma unroll 4
        for (int j = 0; j < 100; ++j) {
            ulonglong2 v = sb2[j];
            rank += (v.x > my) ? 1 : 0;
            rank += (v.y > my) ? 1 : 0;
        }
        rank += __shfl_xor_sync(0xffffffffu, rank, 1);
        if (p == 0) {
            unsigned int k = (unsigned int)(my >> 32);
            unsigned int idx = ~(unsigned int)my;
            float sc = ikey(k);
            float4 pr = reinterpret_cast<const float4*>(priors)[idx];
            const float2* pp2 = reinterpret_cast<const float2*>(pb + (size_t)idx * 6);
            float2 ab = pp2[0];
            float2 cd = pp2[1];
            float2 ef = pp2[2];
            float cx = pr.x + ab.x * 0.1f * pr.z;
            float cy = pr.y + ab.y * 0.1f * pr.w;
            float w  = pr.z * expf(cd.x * 0.2f);
            float h  = pr.w * expf(cd.y * 0.2f);
            float4 bx = make_float4(cx - 0.5f * w, cy - 0.5f * h, cx + 0.5f * w, cy + 0.5f * h);
            s.cbox[rank]  = bx;
            s.carea[rank] = (bx.z - bx.x) * (bx.w - bx.y);
            s.cscore[rank] = sc;
            s.clabel[rank] = (ef.y > ef.x) ? 1.0f : 0.0f;
            if (!(sc > CONF_TH)) atomicOr(&s.keepw[rank >> 5], 1u << (rank & 31));
        }
    }
    __syncthreads();

    // ---------- suppression bit matrix: 2 rows per warp-pass ----------
    {
        int wi = t >> 5;
        int lane = t & 31;
        for (int ip = wi; ip < TOPK / 2; ip += 32) {
            int iA = 2 * ip, iB = iA + 1;
            float4 bA = s.cbox[iA]; float aA = s.carea[iA];
            float4 bB = s.cbox[iB]; float aB = s.carea[iB];
            int w0 = iA >> 5;
            for (int word = w0; word < 13; ++word) {
                int j = (word << 5) | lane;
                float4 bj = s.cbox[j];
                float aj = s.carea[j];
                // row A
                float iwA = fmaxf(fminf(bA.z, bj.z) - fmaxf(bA.x, bj.x), 0.0f);
                float ihA = fmaxf(fminf(bA.w, bj.w) - fmaxf(bA.y, bj.y), 0.0f);
                float inA = iwA * ihA;
                float ssA = aA + aj;
                float mA  = __fmaf_rn(3.0f, inA, -ssA);
                float tA  = 1e-4f * ssA + 1e-20f;
                bool supA;
                if (mA > tA)        supA = true;
                else if (mA >= -tA) supA = (inA / (ssA - inA + 1e-12f)) > NMS_TH;
                else                supA = false;
                // row B
                float iwB = fmaxf(fminf(bB.z, bj.z) - fmaxf(bB.x, bj.x), 0.0f);
                float ihB = fmaxf(fminf(bB.w, bj.w) - fmaxf(bB.y, bj.y), 0.0f);
                float inB = iwB * ihB;
                float ssB = aB + aj;
                float mB  = __fmaf_rn(3.0f, inB, -ssB);
                float tB  = 1e-4f * ssB + 1e-20f;
                bool supB;
                if (mB > tB)        supB = true;
                else if (mB >= -tB) supB = (inB / (ssB - inB + 1e-12f)) > NMS_TH;
                else                supB = false;
                unsigned int balA = __ballot_sync(0xffffffffu, supA);
                unsigned int balB = __ballot_sync(0xffffffffu, supB);
                if (lane == 0) {
                    s.u.sup[iA * 16 + word] = balA & rowmask(iA, word);
                    s.u.sup[iB * 16 + word] = balB & rowmask(iB, word);
                }
            }
        }
    }
    __syncthreads();

    // ---------- single-warp greedy NMS reduce (no block barriers inside) ----------
    if (t < 32) {
        int lane = t;
        unsigned int rm = (lane < 13) ? s.keepw[lane] : 0u;
#pragma unroll 1
        for (int g = 0; g < 13; ++g) {
            unsigned int m = __shfl_sync(0xffffffffu, rm, g);
            const unsigned int* rowg = &s.u.sup[(g * 32) * 16 + g];
#pragma unroll
            for (int ch = 0; ch < 4; ++ch) {
                unsigned int rr[8];
#pragma unroll
                for (int q = 0; q < 8; ++q) rr[q] = rowg[(ch * 8 + q) * 16];
#pragma unroll
                for (int q = 0; q < 8; ++q) {
                    int bb = ch * 8 + q;
                    if (!((m >> bb) & 1u)) m |= rr[q];
                }
            }
            if (lane > g && lane < 13) {
                unsigned int acc = 0;
                const unsigned int* col = &s.u.sup[(g * 32) * 16 + lane];
#pragma unroll
                for (int r = 0; r < 32; ++r) {
                    unsigned int v = col[r * 16];
                    acc |= ((m >> r) & 1u) ? 0u : v;
                }
                rm |= acc;
            }
            if (lane == g) rm = m;
        }
        if (lane < 13) s.keepw[lane] = rm;
    }
    __syncthreads();

    // ---------- output: kept-only compaction + warp-uniform pair-split ranking ----------
    if (t == 0) {
        unsigned int acc = 0;
#pragma unroll
        for (int w = 0; w < 13; ++w) { s.woff[w] = acc; acc += (unsigned)__popc(~s.keepw[w]); }
        s.s_mkept = acc;
    }
    __syncthreads();
    int mk = (int)s.s_mkept;
    if (t < TOPK) {
        bool kp = !((s.keepw[t >> 5] >> (t & 31)) & 1u);
        if (kp) {
            unsigned int before = (unsigned)__popc(~s.keepw[t >> 5] & ((1u << (t & 31)) - 1u));
            int pos = (int)(s.woff[t >> 5] + before);
            s.sortbuf[pos] = ((unsigned long long)__float_as_uint(s.cscore[t]) << 32) | (unsigned int)t;
        }
    }
    if (t < 512 && t >= mk) s.sortbuf[t] = 0xFFFFFFFFFFFFFFFFull;
    __syncthreads();
    {
        int tot2 = 2 * mk;                 // even -> lane pairs both active/inactive
        int tlim2 = (tot2 + 31) & ~31;     // warp-aligned participation
        if (t < tlim2) {
            int e = t >> 1;                 // e <= 415 < 512 (padded region valid)
            int p = t & 1;
            bool act = t < tot2;
            unsigned long long my = s.sortbuf[e];
            const ulonglong2* sb2 = reinterpret_cast<const ulonglong2*>(s.sortbuf);
            int vreal = (mk + 1) >> 1;
            int jmax = vreal - p * 128;
            jmax = jmax < 0 ? 0 : (jmax > 128 ? 128 : jmax);
            int rank = 0;
            for (int j = 0; j < jmax; ++j) {
                ulonglong2 v = sb2[p * 128 + j];
                rank += (v.x < my) ? 1 : 0;
                rank += (v.y < my) ? 1 : 0;
            }
            rank += __shfl_xor_sync(0xffffffffu, rank, 1);
            if (act && p == 0 && rank < KEEPK) {
                int c = (int)(unsigned int)(my & 0xffffffffu);
                float4 bx = s.cbox[c];
                float* o = out + ((size_t)b * KEEPK + rank) * 6;
                o[0] = s.clabel[c];
                o[1] = s.cscore[c];
                o[2] = bx.x; o[3] = bx.y; o[4] = bx.z; o[5] = bx.w;
            }
        }
    }
    if (t < KEEPK && t >= mk) {
        float* o = out + ((size_t)b * KEEPK + t) * 6;
        o[0] = 0.0f; o[1] = 0.0f; o[2] = 0.0f;
        o[3] = 0.0f; o[4] = 0.0f; o[5] = 0.0f;
    }
}

extern "C" void kernel_launch(void* const* d_in, const int* in_sizes, int n_in,
                              void* d_out, int out_size) {
    const float* pred = (const float*)d_in[0];
    const float* pri  = (const float*)d_in[1];
    if (n_in >= 2 && in_sizes[0] < in_sizes[1]) {
        const float* tmp = pred; pred = pri; pri = tmp;
    }
    float* out = (float*)d_out;
    int gridA = (NB * NP) / (NTH * APT);   // 512 blocks, 4 per image
    key_hist_kernel<<<gridA, NTH>>>(pred);
    box_selector_kernel<<<NB, NTH>>>(pred, pri, out);
}

// round 15
// speedup vs baseline: 1.3322x; 1.0228x over previous
#include <cuda_runtime.h>
#include <cstdint>

#define NP      32768
#define NB      128
#define NC      6
#define TOPK    400
#define KEEPK   200
#define NTH     1024
#define EQCAP   2048
#define EQ2CAP  512
#define APT     8
#define SUPROWS 416
#define CONF_TH 0.5f
#define NMS_TH  0.5f
#define BIGF    1.0e9f
#define NEGF    (-1.0e9f)

// global scratch (static arrays, zero-initialized at module load; no runtime alloc)
__device__ unsigned int g_keys[(size_t)NB * NP];     // 16 MB
__device__ unsigned int g_hist[(size_t)NB * 4096];   // 2 MB

__device__ __forceinline__ unsigned int fkey(float x) {
    unsigned int u = __float_as_uint(x);
    return (u & 0x80000000u) ? ~u : (u | 0x80000000u);
}
__device__ __forceinline__ float ikey(unsigned int k) {
    unsigned int u = (k & 0x80000000u) ? (k & 0x7fffffffu) : ~k;
    return __uint_as_float(u);
}
__device__ __forceinline__ unsigned long long packci(unsigned int k, unsigned int idx) {
    return ((unsigned long long)k << 32) | (unsigned int)(~idx);
}
// bits j (= w*32+l) with j > i within word w of row i
__device__ __forceinline__ unsigned int rowmask(int i, int w) {
    int wi = i >> 5;
    if (w > wi) return 0xFFFFFFFFu;
    if (w < wi) return 0u;
    return ~(unsigned int)(((unsigned long long)2 << (i & 31)) - 1ull);
}

// ---------------- kernel A: streaming keys + per-image histogram ----------------
// __ldcs on pred is LOAD-BEARING: evict-first keeps the 96MB stream out of L2,
// preserving L2 residency for g_keys across graph replays (R12 vs R13: ~20us).
__global__ __launch_bounds__(NTH, 2)
void key_hist_kernel(const float* __restrict__ pred) {
    __shared__ unsigned int h[4096];
    int t = threadIdx.x;
    for (int i = t; i < 4096; i += NTH) h[i] = 0;
    __syncthreads();
    int img = blockIdx.x >> 2;
    int base = blockIdx.x * (NTH * APT) + t;
#pragma unroll
    for (int j = 0; j < APT; ++j) {
        int i = base + j * NTH;
        float2 cf = __ldcs(reinterpret_cast<const float2*>(pred + (size_t)i * 6 + 4));
        float sc = fmaxf(cf.x, cf.y);
        float m = (sc > CONF_TH) ? sc : NEGF;
        unsigned int k = fkey(m);
        g_keys[i] = k;
        unsigned int bin = k >> 20;
        unsigned int mm = __match_any_sync(0xffffffffu, bin);
        int leader = __ffs(mm) - 1;
        if ((t & 31) == leader) atomicAdd(&h[bin], (unsigned int)__popc(mm));
    }
    __syncthreads();
    for (int i = t; i < 4096; i += NTH) {
        unsigned int v = h[i];
        if (v) atomicAdd(&g_hist[(size_t)img * 4096 + i], v);
    }
}

// ---------------- kernel B: per-image selection + NMS ----------------
struct __align__(16) SmemT {
    union __align__(16) {
        struct {
            unsigned int hist[4096];   // 16 KB
            unsigned int sscan[64];
        } sel;
        struct { unsigned long long eq[EQCAP]; unsigned long long eq2[EQ2CAP]; } eqs;  // 20 KB
        unsigned int sup[SUPROWS * 16];  // 26.6 KB (13 words used per row)
    } u;
    unsigned long long sortbuf[512];
    float4 cbox[SUPROWS];     // rows 400..415 zeroed
    float  carea[SUPROWS];
    float  cscore[TOPK];
    float  clabel[TOPK];
    unsigned int hist2[256];  // second-level eq histogram (outside union!)
    unsigned int keepw[16];
    unsigned int woff[14];
    unsigned int s_mkept;
    int s_bin;
    int s_gt;
    int s_d2;
    unsigned int s_g2;
    unsigned int s_cnt;
    unsigned int s_eq;
    unsigned int s_cnt2;
    unsigned int s_eq2;
};

__device__ void find_bin(SmemT& s, int K, int& bin_out, int& gt_out) {
    int t = threadIdx.x;
    int lane = t & 31;
    int w = t >> 5;
    unsigned int c[4];
    unsigned int sum = 0;
#pragma unroll
    for (int j = 0; j < 4; j++) { c[j] = s.u.sel.hist[4 * t + j]; sum += c[j]; }
    unsigned int suf = sum;
#pragma unroll
    for (int off = 1; off < 32; off <<= 1) {
        unsigned int v = __shfl_down_sync(0xffffffffu, suf, off);
        if (lane + off < 32) suf += v;
    }
    if (lane == 0) s.u.sel.sscan[w] = suf;
    if (t == 0) s.s_bin = -1;
    __syncthreads();
    if (w == 0) {
        unsigned int wt = s.u.sel.sscan[lane];
        unsigned int ws = wt;
#pragma unroll
        for (int off = 1; off < 32; off <<= 1) {
            unsigned int v = __shfl_down_sync(0xffffffffu, ws, off);
            if (lane + off < 32) ws += v;
        }
        s.u.sel.sscan[32 + lane] = ws - wt;
    }
    __syncthreads();
    unsigned int after = (suf - sum) + s.u.sel.sscan[32 + w];
    unsigned int run = after;
    int best = -1;
    unsigned int bestgt = 0;
#pragma unroll
    for (int j = 3; j >= 0; j--) {
        unsigned int cnt = c[j];
        if (best < 0 && run + cnt >= (unsigned int)K) { best = 4 * t + j; bestgt = run; }
        run += cnt;
    }
    if (best >= 0) atomicMax(&s.s_bin, best);
    __syncthreads();
    if (best >= 0 && best == s.s_bin) s.s_gt = (int)bestgt;
    __syncthreads();
    bin_out = s.s_bin;
    gt_out = s.s_gt;
}

__global__ __launch_bounds__(NTH, 1)
void box_selector_kernel(const float* __restrict__ pred,
                         const float* __restrict__ priors,
                         float* __restrict__ out) {
    __shared__ SmemT s;
    const int t = threadIdx.x;
    const int b = blockIdx.x;
    const float* pb = pred + (size_t)b * NP * NC;
    const unsigned int* keys = g_keys + (size_t)b * NP;

    // ---------- init + hist load (re-zero global hist for next launch) ----------
    if (t < 16) {
        s.keepw[t] = (t == 12) ? 0xFFFF0000u : 0u;
        s.cbox[TOPK + t] = make_float4(0.f, 0.f, 0.f, 0.f);
        s.carea[TOPK + t] = 0.f;
    }
    if (t < 256) s.hist2[t] = 0u;
    for (int i = t; i < 4096; i += NTH) {
        s.u.sel.hist[i] = g_hist[(size_t)b * 4096 + i];
        g_hist[(size_t)b * 4096 + i] = 0u;
    }
    __syncthreads();
    int d1, g1;
    find_bin(s, TOPK, d1, g1);
    int k1 = TOPK - g1;

    // ---------- merged scan: >d1 -> sortbuf (packed), ==d1 -> eq (packed) ----------
    if (t == 0) { s.s_cnt = 0; s.s_eq = 0; }
    __syncthreads();
    {
        const uint4* keys4 = reinterpret_cast<const uint4*>(keys);
#pragma unroll
        for (int j = 0; j < (NP / 4) / NTH; ++j) {
            int n4 = t + j * NTH;
            uint4 kv = keys4[n4];
            int base = n4 * 4;
            unsigned int kk[4] = {kv.x, kv.y, kv.z, kv.w};
#pragma unroll
            for (int l = 0; l < 4; ++l) {
                unsigned int k = kk[l];
                int top = (int)(k >> 20);
                if (top > d1) {
                    unsigned int p = atomicAdd(&s.s_cnt, 1u);
                    s.sortbuf[p] = packci(k, (unsigned int)(base + l));
                } else if (top == d1) {
                    unsigned int e = atomicAdd(&s.s_eq, 1u);
                    if (e < EQCAP) s.u.eqs.eq[e] = packci(k, (unsigned int)(base + l));
                }
            }
        }
    }
    __syncthreads();
    int eqcnt = (int)s.s_eq;

    if (eqcnt <= EQCAP) {
        // ---- two-level refine: 256-bin histogram of key bits [12:19] ----
        for (int me = t; me < eqcnt; me += NTH)
            atomicAdd(&s.hist2[(unsigned int)((s.u.eqs.eq[me] >> 44) & 0xFFu)], 1u);
        __syncthreads();
        if (t < 32) {
            unsigned int c[8];
            unsigned int sum = 0;
#pragma unroll
            for (int q = 0; q < 8; ++q) { c[q] = s.hist2[8 * t + q]; sum += c[q]; }
            unsigned int suf = sum;
#pragma unroll
            for (int off = 1; off < 32; off <<= 1) {
                unsigned int v = __shfl_down_sync(0xffffffffu, suf, off);
                if (t + off < 32) suf += v;
            }
            unsigned int after = suf - sum;
            unsigned int run = after;
            int best = -1;
            unsigned int bg = 0;
#pragma unroll
            for (int q = 7; q >= 0; --q) {
                unsigned int cnt = c[q];
                if (best < 0 && run + cnt >= (unsigned int)k1) { best = 8 * t + q; bg = run; }
                run += cnt;
            }
            int bmax = best;
#pragma unroll
            for (int off = 16; off; off >>= 1) bmax = max(bmax, __shfl_xor_sync(0xffffffffu, bmax, off));
            if (best >= 0 && best == bmax) { s.s_d2 = best; s.s_g2 = bg; }
        }
        if (t == 0) { s.s_cnt2 = 0; s.s_eq2 = 0; }
        __syncthreads();
        int d2 = s.s_d2;
        int k2 = k1 - (int)s.s_g2;
        int c2 = (int)s.hist2[d2];

        if (c2 <= EQ2CAP) {
            for (int me = t; me < eqcnt; me += NTH) {
                unsigned long long v = s.u.eqs.eq[me];
                int mid = (int)((v >> 44) & 0xFFu);
                if (mid > d2) {
                    unsigned int p = atomicAdd(&s.s_cnt2, 1u);
                    s.sortbuf[g1 + p] = v;
                } else if (mid == d2) {
                    unsigned int e = atomicAdd(&s.s_eq2, 1u);
                    s.u.eqs.eq2[e] = v;
                }
            }
            __syncthreads();
            // exact rank of ties (c2 typically tiny)
            for (int me = t; me < c2; me += NTH) {
                unsigned long long v = s.u.eqs.eq2[me];
                int rank = 0;
                for (int j = 0; j < c2; ++j) rank += (s.u.eqs.eq2[j] > v) ? 1 : 0;
                if (rank < k2) {
                    unsigned int p = atomicAdd(&s.s_cnt2, 1u);
                    s.sortbuf[g1 + p] = v;
                }
            }
        } else {
            // pathological tie storm: direct rank among mid==d2 over the full eq
            for (int me = t; me < eqcnt; me += NTH) {
                unsigned long long v = s.u.eqs.eq[me];
                int mid = (int)((v >> 44) & 0xFFu);
                if (mid > d2) {
                    unsigned int p = atomicAdd(&s.s_cnt2, 1u);
                    s.sortbuf[g1 + p] = v;
                } else if (mid == d2) {
                    int rank = 0;
                    for (int j = 0; j < eqcnt; ++j) {
                        unsigned long long w2 = s.u.eqs.eq[j];
                        if (((int)((w2 >> 44) & 0xFFu) == d2) && w2 > v) rank++;
                    }
                    if (rank < k2) {
                        unsigned int p = atomicAdd(&s.s_cnt2, 1u);
                        s.sortbuf[g1 + p] = v;
                    }
                }
            }
        }
    } else {
        // ---------- fallback: radix refine within bin d1 from global keys (rare) ----------
        __syncthreads();
        for (int i = t; i < 4096; i += NTH) s.u.sel.hist[i] = 0;
        __syncthreads();
        for (int n = t; n < NP; n += NTH) {
            unsigned int k = keys[n];
            if ((int)(k >> 20) == d1) atomicAdd(&s.u.sel.hist[(k >> 8) & 0xfffu], 1u);
        }
        __syncthreads();
        int d2, g2;
        find_bin(s, k1, d2, g2);
        int k2 = k1 - g2;
        unsigned int P24 = ((unsigned int)d1 << 12) | (unsigned int)d2;
        __syncthreads();
        for (int i = t; i < 4096; i += NTH) s.u.sel.hist[i] = 0;
        __syncthreads();
        for (int n = t; n < NP; n += NTH) {
            unsigned int k = keys[n];
            if ((k >> 8) == P24) atomicAdd(&s.u.sel.hist[k & 0xffu], 1u);
        }
        __syncthreads();
        int d3, g3;
        find_bin(s, k2, d3, g3);
        int need = k2 - g3;
        unsigned int KP = (P24 << 8) | (unsigned int)d3;
        if (t == 0) s.s_cnt = 0;
        __syncthreads();
        for (int n = t; n < NP; n += NTH) {
            unsigned int k = keys[n];
            if ((int)(k >> 20) == d1 && k > KP) {
                unsigned int p = atomicAdd(&s.s_cnt, 1u);
                s.sortbuf[g1 + p] = packci(k, (unsigned int)n);
            }
        }
        __syncthreads();
        if (t < 32) {
            int taken = 0;
            int slot0 = g1 + (k1 - need);
            for (int base2 = 0; base2 < NP && taken < need; base2 += 32) {
                unsigned int k = keys[base2 + t];
                bool e = (k == KP);
                unsigned int bal = __ballot_sync(0xffffffffu, e);
                int rank = __popc(bal & ((1u << t) - 1u));
                if (e && taken + rank < need)
                    s.sortbuf[slot0 + taken + rank] = packci(KP, (unsigned int)(base2 + t));
                taken += __popc(bal);
            }
        }
    }
    __syncthreads();

    // ---------- fused sort1-rank + decode (gather loads hoisted above rank loop) ----------
    if (t < 2 * TOPK) {
        int e = t >> 1;
        int p = t & 1;
        unsigned long long my = s.sortbuf[e];
        unsigned int k = (unsigned int)(my >> 32);
        unsigned int idx = ~(unsigned int)my;
        // issue gather loads early (idx known before ranking) to hide DRAM latency
        float4 pr = make_float4(0.f, 0.f, 0.f, 0.f);
        float2 ab = make_float2(0.f, 0.f), cd = ab, ef = ab;
        if (p == 0) {
            pr = reinterpret_cast<const float4*>(priors)[idx];
            const float2* pp2 = reinterpret_cast<const float2*>(pb + (size_t)idx * 6);
            ab = pp2[0];
            cd = pp2[1];
            ef = pp2[2];
        }
        const ulonglong2* sb2 = reinterpret_cast<const ulonglong2*>(s.sortbuf) + p * 100;
        int rank = 0;
#pragma unroll 4
        for (int j = 0; j < 100; ++j) {
            ulonglong2 v = sb2[j];
            rank += (v.x > my) ? 1 : 0;
            rank += (v.y > my) ? 1 : 0;
        }
        rank += __shfl_xor_sync(0xffffffffu, rank, 1);
        if (p == 0) {
            float sc = ikey(k);
            float cx = pr.x + ab.x * 0.1f * pr.z;
            float cy = pr.y + ab.y * 0.1f * pr.w;
            float w  = pr.z * expf(cd.x * 0.2f);
            float h  = pr.w * expf(cd.y * 0.2f);
            float4 bx = make_float4(cx - 0.5f * w, cy - 0.5f * h, cx + 0.5f * w, cy + 0.5f * h);
            s.cbox[rank]  = bx;
            s.carea[rank] = (bx.z - bx.x) * (bx.w - bx.y);
            s.cscore[rank] = sc;
            s.clabel[rank] = (ef.y > ef.x) ? 1.0f : 0.0f;
            if (!(sc > CONF_TH)) atomicOr(&s.keepw[rank >> 5], 1u << (rank & 31));
        }
    }
    __syncthreads();

    // ---------- suppression bit matrix: 2 rows/warp-pass, cold-path divide ----------
    {
        int wi = t >> 5;
        int lane = t & 31;
        for (int ip = wi; ip < TOPK / 2; ip += 32) {
            int iA = 2 * ip, iB = iA + 1;
            float4 bA = s.cbox[iA]; float aA = s.carea[iA];
            float4 bB = s.cbox[iB]; float aB = s.carea[iB];
            int w0 = iA >> 5;
            for (int word = w0; word < 13; ++word) {
                int j = (word << 5) | lane;
                float4 bj = s.cbox[j];
                float aj = s.carea[j];
                // row A: iou > 0.5  <=>  3*inter > ssum (exact reals); band -> exact div
                float iwA = fmaxf(fminf(bA.z, bj.z) - fmaxf(bA.x, bj.x), 0.0f);
                float ihA = fmaxf(fminf(bA.w, bj.w) - fmaxf(bA.y, bj.y), 0.0f);
                float inA = iwA * ihA;
                float ssA = aA + aj;
                float mA  = __fmaf_rn(3.0f, inA, -ssA);
                float tA  = 1e-4f * ssA + 1e-20f;
                bool supA  = mA > tA;
                bool bandA = fabsf(mA) <= tA;
                // row B
                float iwB = fmaxf(fminf(bB.z, bj.z) - fmaxf(bB.x, bj.x), 0.0f);
                float ihB = fmaxf(fminf(bB.w, bj.w) - fmaxf(bB.y, bj.y), 0.0f);
                float inB = iwB * ihB;
                float ssB = aB + aj;
                float mB  = __fmaf_rn(3.0f, inB, -ssB);
                float tB  = 1e-4f * ssB + 1e-20f;
                bool supB  = mB > tB;
                bool bandB = fabsf(mB) <= tB;
                // warp-uniform cold path: the expensive exact divide almost never issues
                if (__ballot_sync(0xffffffffu, bandA || bandB)) {
                    if (bandA) supA = (inA / (ssA - inA + 1e-12f)) > NMS_TH;
                    if (bandB) supB = (inB / (ssB - inB + 1e-12f)) > NMS_TH;
                }
                unsigned int balA = __ballot_sync(0xffffffffu, supA);
                unsigned int balB = __ballot_sync(0xffffffffu, supB);
                if (lane == 0) {
                    s.u.sup[iA * 16 + word] = balA & rowmask(iA, word);
                    s.u.sup[iB * 16 + word] = balB & rowmask(iB, word);
                }
            }
        }
    }
    __syncthreads();

    // ---------- single-warp greedy NMS reduce (no block barriers inside) ----------
    if (t < 32) {
        int lane = t;
        unsigned int rm = (lane < 13) ? s.keepw[lane] : 0u;
#pragma unroll 1
        for (int g = 0; g < 13; ++g) {
            unsigned int m = __shfl_sync(0xffffffffu, rm, g);
            const unsigned int* rowg = &s.u.sup[(g * 32) * 16 + g];
#pragma unroll
            for (int ch = 0; ch < 4; ++ch) {
                unsigned int rr[8];
#pragma unroll
                for (int q = 0; q < 8; ++q) rr[q] = rowg[(ch * 8 + q) * 16];
#pragma unroll
                for (int q = 0; q < 8; ++q) {
                    int bb = ch * 8 + q;
                    if (!((m >> bb) & 1u)) m |= rr[q];
                }
            }
            if (lane > g && lane < 13) {
                unsigned int acc = 0;
                const unsigned int* col = &s.u.sup[(g * 32) * 16 + lane];
#pragma unroll
                for (int r = 0; r < 32; ++r) {
                    unsigned int v = col[r * 16];
                    acc |= ((m >> r) & 1u) ? 0u : v;
                }
                rm |= acc;
            }
            if (lane == g) rm = m;
        }
        if (lane < 13) s.keepw[lane] = rm;
    }
    __syncthreads();

    // ---------- output: kept-only compaction + warp-uniform pair-split ranking ----------
    if (t == 0) {
        unsigned int acc = 0;
#pragma unroll
        for (int w = 0; w < 13; ++w) { s.woff[w] = acc; acc += (unsigned)__popc(~s.keepw[w]); }
        s.s_mkept = acc;
    }
    __syncthreads();
    int mk = (int)s.s_mkept;
    if (t < TOPK) {
        bool kp = !((s.keepw[t >> 5] >> (t & 31)) & 1u);
        if (kp) {
            unsigned int before = (unsigned)__popc(~s.keepw[t >> 5] & ((1u << (t & 31)) - 1u));
            int pos = (int)(s.woff[t >> 5] + before);
            s.sortbuf[pos] = ((unsigned long long)__float_as_uint(s.cscore[t]) << 32) | (unsigned int)t;
        }
    }
    if (t < 512 && t >= mk) s.sortbuf[t] = 0xFFFFFFFFFFFFFFFFull;
    __syncthreads();
    {
        int tot2 = 2 * mk;                 // even -> lane pairs both active/inactive
        int tlim2 = (tot2 + 31) & ~31;     // warp-aligned participation
        if (t < tlim2) {
            int e = t >> 1;                 // e <= 415 < 512 (padded region valid)
            int p = t & 1;
            bool act = t < tot2;
            unsigned long long my = s.sortbuf[e];
            const ulonglong2* sb2 = reinterpret_cast<const ulonglong2*>(s.sortbuf);
            int vreal = (mk + 1) >> 1;
            int jmax = vreal - p * 128;
            jmax = jmax < 0 ? 0 : (jmax > 128 ? 128 : jmax);
            int rank = 0;
            for (int j = 0; j < jmax; ++j) {
                ulonglong2 v = sb2[p * 128 + j];
                rank += (v.x < my) ? 1 : 0;
                rank += (v.y < my) ? 1 : 0;
            }
            rank += __shfl_xor_sync(0xffffffffu, rank, 1);
            if (act && p == 0 && rank < KEEPK) {
                int c = (int)(unsigned int)(my & 0xffffffffu);
                float4 bx = s.cbox[c];
                float* o = out + ((size_t)b * KEEPK + rank) * 6;
                o[0] = s.clabel[c];
                o[1] = s.cscore[c];
                o[2] = bx.x; o[3] = bx.y; o[4] = bx.z; o[5] = bx.w;
            }
        }
    }
    if (t < KEEPK && t >= mk) {
        float* o = out + ((size_t)b * KEEPK + t) * 6;
        o[0] = 0.0f; o[1] = 0.0f; o[2] = 0.0f;
        o[3] = 0.0f; o[4] = 0.0f; o[5] = 0.0f;
    }
}

extern "C" void kernel_launch(void* const* d_in, const int* in_sizes, int n_in,
                              void* d_out, int out_size) {
    const float* pred = (const float*)d_in[0];
    const float* pri  = (const float*)d_in[1];
    if (n_in >= 2 && in_sizes[0] < in_sizes[1]) {
        const float* tmp = pred; pred = pri; pri = tmp;
    }
    float* out = (float*)d_out;
    int gridA = (NB * NP) / (NTH * APT);   // 512 blocks, 4 per image
    key_hist_kernel<<<gridA, NTH>>>(pred);
    box_selector_kernel<<<NB, NTH>>>(pred, pri, out);
}